// round 14
// baseline (speedup 1.0000x reference)
#include <cuda_runtime.h>
#include <cstdint>

// ---------------------------------------------------------------------------
// GRU (H=1, single step) over N = B*A = 1,048,576 rows of C=64 floats.
//   x = row[1:64], h0 = row[0]
//   gi = x @ W_ih^T + b_ih ; gh = h0 * W_hh + b_hh
//   r = sig(gi_r+gh_r); z = sig(gi_z+gh_z); n = tanh(gi_n + r*gh_n)
//   h1 = (1-z)*n + z*h0 ; out = h1*w_lin + b_lin
//
// PERSISTENT single-wave kernel, 888 CTAs, DOUBLE-BUFFERED 64-row chunks:
//   prologue: DMA chunk c -> buf0, chunk c+stride -> buf1 (cp.async.cg)
//   loop:     wait_group 1 (oldest buf ready) -> compute 64 rows
//             (threads 0..63, one per row, conflict-free ROW_PAD=17 layout)
//             -> barrier -> reissue freed buf with chunk c+2*stride.
//   A CTA always has 1-2 commit groups (16-32KB) in flight: no DMA dead time.
// Channel-0 weight forced to 0 so h0 rides the same vector load.
// ---------------------------------------------------------------------------

static __device__ __forceinline__ float sigmoidf_fast(float x) {
    return 1.0f / (1.0f + __expf(-x));
}

static __device__ __forceinline__ uint32_t smem_u32(const void* p) {
    return (uint32_t)__cvta_generic_to_shared(p);
}

static __device__ __forceinline__ void cp_async16(uint32_t dst, const void* src) {
    asm volatile("cp.async.cg.shared.global [%0], [%1], 16;"
                 :: "r"(dst), "l"(src) : "memory");
}

#define TPB          128         // threads per block
#define ROWS_PER_CHK 64          // rows per chunk (one buffer)
#define F4_PER_ROW   16          // 64 floats
#define ROW_PAD      17          // padded row stride in float4 (conflict-free)
#define CHK_F4       (ROWS_PER_CHK * F4_PER_ROW)   // 1024 float4 per chunk
#define BUF_F4       (ROWS_PER_CHK * ROW_PAD)      // 1088 float4 per buffer
#define NSM          148
#define CTAS_PER_SM  6

// Issue one chunk's DMA: 128 threads x 8 float4, coalesced.
static __device__ __forceinline__ void issue_chunk(
    const float4* __restrict__ in4, uint32_t buf_base, int chunk, int tid) {
    const float4* gp = in4 + (size_t)chunk * CHK_F4;
    #pragma unroll
    for (int k = 0; k < 8; k++) {
        int f = k * TPB + tid;
        cp_async16(buf_base + (uint32_t)((f >> 4) * ROW_PAD + (f & 15)) * 16u,
                   gp + f);
    }
}

__global__ __launch_bounds__(TPB) void gru_main_kernel(
    const float* __restrict__ in,
    const float* __restrict__ W_ih,   // [3][63] row-major
    const float* __restrict__ W_hh,   // [3]
    const float* __restrict__ b_ih,   // [3]
    const float* __restrict__ b_hh,   // [3]
    const float* __restrict__ w_lin,  // [1]
    const float* __restrict__ b_lin,  // [1]
    float* __restrict__ out,
    int nchunks) {
    __shared__ float4 s_buf[2][BUF_F4];          // 2 x 17,408 B = 34,816 B
    __shared__ float4 s_wr[16], s_wz[16], s_wn[16];
    __shared__ float  s_sc[9];

    const int  tid    = threadIdx.x;
    const int  stride = gridDim.x;
    const float4* in4 = reinterpret_cast<const float4*>(in);
    uint32_t   sb0    = smem_u32(s_buf[0]);
    uint32_t   sb1    = smem_u32(s_buf[1]);

    // ---- Prologue: queue two chunks, repack weights under the DMA ----
    int c0 = blockIdx.x;
    issue_chunk(in4, sb0, c0, tid);
    asm volatile("cp.async.commit_group;" ::: "memory");
    if (c0 + stride < nchunks) issue_chunk(in4, sb1, c0 + stride, tid);
    asm volatile("cp.async.commit_group;" ::: "memory");

    if (tid < 16) {          // channel c = 4*tid+k; c==0 -> weight 0
        float4 wr, wz, wn;
        float* pr = (float*)&wr; float* pz = (float*)&wz; float* pn = (float*)&wn;
        #pragma unroll
        for (int k = 0; k < 4; k++) {
            int c = 4 * tid + k;
            if (c == 0) { pr[k] = 0.f; pz[k] = 0.f; pn[k] = 0.f; }
            else {
                pr[k] = __ldg(&W_ih[0 * 63 + (c - 1)]);
                pz[k] = __ldg(&W_ih[1 * 63 + (c - 1)]);
                pn[k] = __ldg(&W_ih[2 * 63 + (c - 1)]);
            }
        }
        s_wr[tid] = wr; s_wz[tid] = wz; s_wn[tid] = wn;
    } else if (tid == 16) {
        s_sc[0] = __ldg(&W_hh[0]);
        s_sc[1] = __ldg(&W_hh[1]);
        s_sc[2] = __ldg(&W_hh[2]);
        s_sc[3] = __ldg(&b_ih[0]) + __ldg(&b_hh[0]);   // r bias sum
        s_sc[4] = __ldg(&b_ih[1]) + __ldg(&b_hh[1]);   // z bias sum
        s_sc[5] = __ldg(&b_ih[2]);                     // n: gi bias
        s_sc[6] = __ldg(&b_hh[2]);                     // n: gh bias (inside r*)
        s_sc[7] = __ldg(&w_lin[0]);
        s_sc[8] = __ldg(&b_lin[0]);
    }

    // ---- Steady state: compute oldest buffer, reissue it immediately ----
    int buf = 0;
    for (int c = c0; c < nchunks; c += stride, buf ^= 1) {
        asm volatile("cp.async.wait_group 1;" ::: "memory");
        __syncthreads();     // publishes oldest buffer (+ weights on iter 0)

        if (tid < ROWS_PER_CHK) {
            const float4* myrow = s_buf[buf] + tid * ROW_PAD;
            float4 v0 = myrow[0];
            float  h0 = v0.x;                    // channel 0 (weight forced 0)
            float4 w;
            w = s_wr[0]; float ar = v0.x*w.x + v0.y*w.y + v0.z*w.z + v0.w*w.w;
            w = s_wz[0]; float az = v0.x*w.x + v0.y*w.y + v0.z*w.z + v0.w*w.w;
            w = s_wn[0]; float an = v0.x*w.x + v0.y*w.y + v0.z*w.z + v0.w*w.w;
            #pragma unroll
            for (int j = 1; j < F4_PER_ROW; j++) {
                float4 v = myrow[j];
                w = s_wr[j]; ar += v.x*w.x + v.y*w.y + v.z*w.z + v.w*w.w;
                w = s_wz[j]; az += v.x*w.x + v.y*w.y + v.z*w.z + v.w*w.w;
                w = s_wn[j]; an += v.x*w.x + v.y*w.y + v.z*w.z + v.w*w.w;
            }
            float r  = sigmoidf_fast(ar + h0 * s_sc[0] + s_sc[3]);
            float z  = sigmoidf_fast(az + h0 * s_sc[1] + s_sc[4]);
            float n  = tanhf(an + s_sc[5] + r * (h0 * s_sc[2] + s_sc[6]));
            float h1 = (1.0f - z) * n + z * h0;
            out[(size_t)c * ROWS_PER_CHK + tid] = h1 * s_sc[7] + s_sc[8];
        }

        __syncthreads();     // all reads of this buffer done -> safe to refill

        int next2 = c + 2 * stride;
        if (next2 < nchunks)
            issue_chunk(in4, buf ? sb1 : sb0, next2, tid);
        // Always commit (possibly empty) to keep group accounting exact.
        asm volatile("cp.async.commit_group;" ::: "memory");
    }
}

extern "C" void kernel_launch(void* const* d_in, const int* in_sizes, int n_in,
                              void* d_out, int out_size) {
    const float* inputs = (const float*)d_in[0];
    const float* W_ih   = (const float*)d_in[1];
    const float* W_hh   = (const float*)d_in[2];
    const float* b_ih   = (const float*)d_in[3];
    const float* b_hh   = (const float*)d_in[4];
    const float* w_lin  = (const float*)d_in[5];
    const float* b_lin  = (const float*)d_in[6];
    float* out = (float*)d_out;

    int nrows   = in_sizes[0] / 64;              // B*A = 1,048,576
    int nchunks = nrows / ROWS_PER_CHK;          // 16384 (exact)

    int blocks = NSM * CTAS_PER_SM;              // 888: single wave at occ 6
    if (blocks > nchunks) blocks = nchunks;

    gru_main_kernel<<<blocks, TPB>>>(inputs, W_ih, W_hh, b_ih, b_hh,
                                     w_lin, b_lin, out, nchunks);
}